// round 6
// baseline (speedup 1.0000x reference)
#include <cuda_runtime.h>
#include <cuda_fp16.h>

// Sinkhorn on s[B=32, N=1024, M=1024], MAX_ITER=15, EPS=1e-4.
//
// Single persistent kernel, factored form s_t = r_i * s0_ij * c_j.
// Block k of batch b owns rows [64k,64k+64) for all phases (block-private
// fp16 slice). Thread t owns columns [8t, 8t+8) for all phases, so the
// column scaling c lives entirely in 8 registers per thread.
// Row steps: per-thread partial dots -> smem q2d -> warp reduce -> r_i.
// Column steps: per-thread partial column sums -> g_part (double-buffered)
// -> batch-local barrier -> per-thread c_reg update.

#define BB 32
#define NN 1024
#define MM 1024
#define EPSF 1e-4f
#define KB_ 16            // blocks per batch
#define RPB (NN / KB_)    // 64 rows per block
#define TPB 128           // threads per block
#define QPITCH (TPB + 4)  // padded pitch for q2d (132 floats)

__device__ __half2 g_h[(size_t)BB * NN * MM / 2];   // 64 MB fp16 copy
__device__ float g_part[2][BB * KB_ * MM];          // double-buffered partials
__device__ int g_cnt2[BB];                          // zero-init
__device__ int g_flag[BB];                          // monotonic, persists

// ---------------------------------------------------------------------------
// Batch-local barrier: 16 blocks of batch b. Monotonic target continues from
// the persisted flag value, so graph replays need no reset.
__device__ __forceinline__ void batch_barrier(int b, int& nextv) {
    __threadfence();
    __syncthreads();
    nextv += 1;
    if (threadIdx.x == 0) {
        int old = atomicAdd(&g_cnt2[b], 1);
        if (old == KB_ - 1) {
            atomicExch(&g_cnt2[b], 0);
            __threadfence();
            *(volatile int*)&g_flag[b] = nextv;
        } else {
            while (*(volatile int*)&g_flag[b] - nextv < 0) __nanosleep(32);
        }
        __threadfence();
    }
    __syncthreads();
}

// ---------------------------------------------------------------------------
__global__ void __launch_bounds__(TPB, 4)
sinkhorn_kernel(const float* __restrict__ s, float* __restrict__ out) {
    const int bx = blockIdx.x;
    const int b = bx >> 4;         // batch
    const int k = bx & (KB_ - 1);  // block within batch
    const int tid = threadIdx.x;
    const int warp = tid >> 5;
    const int lane = tid & 31;

    __shared__ float q2d[RPB * QPITCH];  // per-(row,thread) q partials
    __shared__ float sr[RPB];            // row scaling r for own rows

    int nextv = *(volatile int*)&g_flag[b];  // barrier base (safe: see R5)

    const size_t row0 = (size_t)(b * NN + k * RPB);
    const uint4* hrow = (const uint4*)(g_h + row0 * (MM / 2)) + tid;
    const size_t HSTRIDE = MM / 8;  // uint4 per row

    // ---------------- it = 0: fp32->fp16 conversion + column partials (r=1)
    float c_reg[8];
    {
        const float4* sp = (const float4*)(s + row0 * MM) + tid * 2;
        uint4* hw = (uint4*)(g_h + row0 * (MM / 2)) + tid;
        float a0 = 0.f, a1 = 0.f, a2 = 0.f, a3 = 0.f;
        float a4 = 0.f, a5 = 0.f, a6 = 0.f, a7 = 0.f;
#pragma unroll 4
        for (int i = 0; i < RPB; i++) {
            float4 va = sp[(size_t)i * (MM / 4)];
            float4 vb = sp[(size_t)i * (MM / 4) + 1];
            __half2 h0 = __floats2half2_rn(va.x, va.y);
            __half2 h1 = __floats2half2_rn(va.z, va.w);
            __half2 h2 = __floats2half2_rn(vb.x, vb.y);
            __half2 h3 = __floats2half2_rn(vb.z, vb.w);
            uint4 o;
            o.x = *(unsigned*)&h0;
            o.y = *(unsigned*)&h1;
            o.z = *(unsigned*)&h2;
            o.w = *(unsigned*)&h3;
            hw[(size_t)i * HSTRIDE] = o;
            a0 += va.x; a1 += va.y; a2 += va.z; a3 += va.w;
            a4 += vb.x; a5 += vb.y; a6 += vb.z; a7 += vb.w;
        }
        float* pp = &g_part[0][((size_t)(b * KB_ + k)) * MM + tid * 8];
        *(float4*)pp = make_float4(a0, a1, a2, a3);
        *(float4*)(pp + 4) = make_float4(a4, a5, a6, a7);
    }
    batch_barrier(b, nextv);

    // c init (c_old = 1): c = 1 / (P + eps), P from buffer 0 partials.
    {
        float p[8];
#pragma unroll
        for (int e = 0; e < 8; e++) p[e] = 0.f;
#pragma unroll
        for (int q = 0; q < KB_; q++) {
            const float* pp = &g_part[0][((size_t)(b * KB_ + q)) * MM + tid * 8];
            float4 v0 = __ldcg((const float4*)pp);
            float4 v1 = __ldcg((const float4*)(pp + 4));
            p[0] += v0.x; p[1] += v0.y; p[2] += v0.z; p[3] += v0.w;
            p[4] += v1.x; p[5] += v1.y; p[6] += v1.z; p[7] += v1.w;
        }
#pragma unroll
        for (int e = 0; e < 8; e++) c_reg[e] = 1.0f / (p[e] + EPSF);
    }

    // ---------------- 7 x fused (row step it=2h+1, col step it=2h+2)
    for (int half = 0; half < 7; half++) {
        // ---- row-q sweep: q2d[i][tid] = sum_e h[i, 8t+e] * c_reg[e]
#pragma unroll 1
        for (int ic = 0; ic < RPB / 8; ic++) {
            uint4 v[8];
#pragma unroll
            for (int ii = 0; ii < 8; ii++)
                v[ii] = hrow[(size_t)(ic * 8 + ii) * HSTRIDE];
#pragma unroll
            for (int ii = 0; ii < 8; ii++) {
                float2 f0 = __half22float2(*(__half2*)&v[ii].x);
                float2 f1 = __half22float2(*(__half2*)&v[ii].y);
                float2 f2 = __half22float2(*(__half2*)&v[ii].z);
                float2 f3 = __half22float2(*(__half2*)&v[ii].w);
                float qa = f0.x * c_reg[0];
                float qb = f0.y * c_reg[1];
                qa = fmaf(f1.x, c_reg[2], qa);
                qb = fmaf(f1.y, c_reg[3], qb);
                qa = fmaf(f2.x, c_reg[4], qa);
                qb = fmaf(f2.y, c_reg[5], qb);
                qa = fmaf(f3.x, c_reg[6], qa);
                qb = fmaf(f3.y, c_reg[7], qb);
                q2d[(ic * 8 + ii) * QPITCH + tid] = qa + qb;
            }
        }
        __syncthreads();

        // ---- q reduce: warp w handles rows [16w, 16w+16); r_i update
#pragma unroll
        for (int rr = 0; rr < RPB / 4 / 8; rr++) {  // 16 rows per warp... 
        }
        {
            const int rbase = warp * (RPB / 4);
#pragma unroll
            for (int ri = 0; ri < RPB / 4; ri++) {
                const int i = rbase + ri;
                const float* qrow = &q2d[i * QPITCH];
                float acc = qrow[lane] + qrow[lane + 32] + qrow[lane + 64] +
                            qrow[lane + 96];
#pragma unroll
                for (int o = 16; o > 0; o >>= 1)
                    acc += __shfl_xor_sync(0xffffffffu, acc, o);
                if (lane == 0) {
                    float r = (half == 0) ? 1.0f : sr[i];
                    sr[i] = r / fmaf(r, acc, EPSF);
                }
            }
        }
        __syncthreads();

        // ---- col sweep: acc[e] += r_i * h[i, 8t+e] over own rows
        const int buf = (half + 1) & 1;
        {
            float acc[8];
#pragma unroll
            for (int e = 0; e < 8; e++) acc[e] = 0.f;
#pragma unroll 1
            for (int ic = 0; ic < RPB / 8; ic++) {
                uint4 v[8];
                float rw[8];
#pragma unroll
                for (int ii = 0; ii < 8; ii++)
                    v[ii] = hrow[(size_t)(ic * 8 + ii) * HSTRIDE];
#pragma unroll
                for (int ii = 0; ii < 8; ii++) rw[ii] = sr[ic * 8 + ii];
#pragma unroll
                for (int ii = 0; ii < 8; ii++) {
                    float2 f0 = __half22float2(*(__half2*)&v[ii].x);
                    float2 f1 = __half22float2(*(__half2*)&v[ii].y);
                    float2 f2 = __half22float2(*(__half2*)&v[ii].z);
                    float2 f3 = __half22float2(*(__half2*)&v[ii].w);
                    acc[0] = fmaf(rw[ii], f0.x, acc[0]);
                    acc[1] = fmaf(rw[ii], f0.y, acc[1]);
                    acc[2] = fmaf(rw[ii], f1.x, acc[2]);
                    acc[3] = fmaf(rw[ii], f1.y, acc[3]);
                    acc[4] = fmaf(rw[ii], f2.x, acc[4]);
                    acc[5] = fmaf(rw[ii], f2.y, acc[5]);
                    acc[6] = fmaf(rw[ii], f3.x, acc[6]);
                    acc[7] = fmaf(rw[ii], f3.y, acc[7]);
                }
            }
            float* pp = &g_part[buf][((size_t)(b * KB_ + k)) * MM + tid * 8];
            *(float4*)pp = make_float4(acc[0], acc[1], acc[2], acc[3]);
            *(float4*)(pp + 4) = make_float4(acc[4], acc[5], acc[6], acc[7]);
        }
        batch_barrier(b, nextv);

        // ---- c_reg update from buffer `buf` (identical order in all blocks)
        {
            float p[8];
#pragma unroll
            for (int e = 0; e < 8; e++) p[e] = 0.f;
#pragma unroll
            for (int q = 0; q < KB_; q++) {
                const float* pp =
                    &g_part[buf][((size_t)(b * KB_ + q)) * MM + tid * 8];
                float4 v0 = __ldcg((const float4*)pp);
                float4 v1 = __ldcg((const float4*)(pp + 4));
                p[0] += v0.x; p[1] += v0.y; p[2] += v0.z; p[3] += v0.w;
                p[4] += v1.x; p[5] += v1.y; p[6] += v1.z; p[7] += v1.w;
            }
#pragma unroll
            for (int e = 0; e < 8; e++)
                c_reg[e] = c_reg[e] / fmaf(c_reg[e], p[e], EPSF);
        }
    }

    // ---------------- finalize: out = r_i * s0_ij * c_j (fp32 source)
    {
        const float4 c40 = make_float4(c_reg[0], c_reg[1], c_reg[2], c_reg[3]);
        const float4 c41 = make_float4(c_reg[4], c_reg[5], c_reg[6], c_reg[7]);
        const float4* sp = (const float4*)(s + row0 * MM) + tid * 2;
        float4* op = (float4*)(out + row0 * MM) + tid * 2;
#pragma unroll 4
        for (int i = 0; i < RPB; i++) {
            const float r = sr[i];
            float4 va = sp[(size_t)i * (MM / 4)];
            float4 vb = sp[(size_t)i * (MM / 4) + 1];
            float4 oa, ob;
            oa.x = r * va.x * c40.x;
            oa.y = r * va.y * c40.y;
            oa.z = r * va.z * c40.z;
            oa.w = r * va.w * c40.w;
            ob.x = r * vb.x * c41.x;
            ob.y = r * vb.y * c41.y;
            ob.z = r * vb.z * c41.z;
            ob.w = r * vb.w * c41.w;
            op[(size_t)i * (MM / 4)] = oa;
            op[(size_t)i * (MM / 4) + 1] = ob;
        }
    }
}

// ---------------------------------------------------------------------------
extern "C" void kernel_launch(void* const* d_in, const int* in_sizes, int n_in,
                              void* d_out, int out_size) {
    const float* s = (const float*)d_in[0];
    float* out = (float*)d_out;
    sinkhorn_kernel<<<BB * KB_, TPB>>>(s, out);
}